// round 15
// baseline (speedup 1.0000x reference)
#include <cuda_runtime.h>

// Fused 3-layer GraphConv, B=524288.
//   A_ENC:  agg[j]  = sum_{i=4j-3..4j+2} x[i mod 40]
//   A_PRED: agg2[j] = z1[j] + w*(z1[j-1] + z1[j+1]),  w = exp(-1/9)
//   A_DEC:  out[4k]=s[k], out[4k+1]=out[4k+2]=s[k]+s[k+1], out[4k+3]=s[k+1]
//           with s[j] = dot(relu(pred(z1)[j]), dec_rel_w)
//
// R14 = R13 + packed fma.rn.f32x2 paired over the g (input-feature) axis:
//   t[f] += (z[g],z[g+1]) * (W[f][g],W[f][g+1]);  horizontal add at the end.
//   z pairs are free (LDS.128 quads), weight pairs come from constants
//   (LDCU, no regular regs) -> none of R2's broadcast/packed-weight bloat.

#define WPRED 0.8948393168143698f

__constant__ __align__(16) float cW[232];
#define C_ER   0     // enc_root_w  [f*8+g]
#define C_M1   64    // PR + PO
#define C_M2   128   // WPRED * PR
#define C_EWB  192   // float2 pairs {erw[f], erb[f]}  (16 floats)
#define C_PBD  208   // float2 pairs {prb[f], drw[f]}  (16 floats)
#define C_DRB  224
#define C_DRT  225

__device__ __align__(16) float gStage[232];

__global__ void gather_weights(const float* __restrict__ erw, const float* __restrict__ erb,
                               const float* __restrict__ er,  const float* __restrict__ pr,
                               const float* __restrict__ prb, const float* __restrict__ po,
                               const float* __restrict__ drw, const float* __restrict__ drb,
                               const float* __restrict__ drt)
{
    const int t = threadIdx.x;
    if (t < 64) {
        gStage[C_ER + t] = er[t];
        gStage[C_M1 + t] = pr[t] + po[t];
        gStage[C_M2 + t] = WPRED * pr[t];
    }
    if (t < 8) {
        gStage[C_EWB + 2 * t]     = erw[t];
        gStage[C_EWB + 2 * t + 1] = erb[t];
        gStage[C_PBD + 2 * t]     = prb[t];
        gStage[C_PBD + 2 * t + 1] = drw[t];
    }
    if (t == 0) { gStage[C_DRB] = drb[0]; gStage[C_DRT] = drt[0]; }
}

typedef unsigned long long ull;
union f2u { float2 f; ull u; };

__device__ __forceinline__ ull ffma2(ull a, ull b, ull c) {
    ull d;
    asm("fma.rn.f32x2 %0, %1, %2, %3;" : "=l"(d) : "l"(a), "l"(b), "l"(c));
    return d;
}
__device__ __forceinline__ ull fadd2(ull a, ull b) {
    ull d;
    asm("add.rn.f32x2 %0, %1, %2;" : "=l"(d) : "l"(a), "l"(b));
    return d;
}
__device__ __forceinline__ ull pack2(float lo, float hi) {
    f2u t; t.f = make_float2(lo, hi); return t.u;
}
__device__ __forceinline__ float hsum2(ull a) {
    f2u t; t.u = a; return t.f.x + t.f.y;
}

__device__ __forceinline__ float4 lds128a(unsigned a) {
    float4 r;
    asm volatile("ld.shared.v4.f32 {%0,%1,%2,%3}, [%4];"
                 : "=f"(r.x), "=f"(r.y), "=f"(r.z), "=f"(r.w) : "r"(a));
    return r;
}
__device__ __forceinline__ void sts128a(unsigned a, float4 v) {
    asm volatile("st.shared.v4.f32 [%0], {%1,%2,%3,%4};"
                 :: "r"(a), "f"(v.x), "f"(v.y), "f"(v.z), "f"(v.w));
}
__device__ __forceinline__ unsigned saddr(const void* p) {
    return (unsigned)__cvta_generic_to_shared(p);
}
// load one z1 row (8 floats) as 4 aligned pairs
__device__ __forceinline__ void load_row_p(unsigned a, ull r[4]) {
    float4 v0 = lds128a(a);
    float4 v1 = lds128a(a + 16);
    r[0] = pack2(v0.x, v0.y); r[1] = pack2(v0.z, v0.w);
    r[2] = pack2(v1.x, v1.y); r[3] = pack2(v1.z, v1.w);
}

template <bool FULL>
__device__ __forceinline__ void body(const float* __restrict__ x,
                                     const float* __restrict__ z,
                                     const float* __restrict__ y,
                                     float* __restrict__ out,
                                     float* buf, int lane, long long e0, int nv)
{
    float* ss = buf;   // alias: reused after z1 dead (32 x stride-11 floats)

    // ===== stage x (coalesced, streaming), rows padded to 44 floats =====
    {
        const float4* xg = (const float4*)(x + e0 * 40);
        const int lim = nv * 10;
        #pragma unroll
        for (int k = 0; k < 10; k++) {
            int f4 = k * 32 + lane;
            if (FULL || f4 < lim) {
                float4 v = __ldcs(&xg[f4]);
                *(float4*)&buf[(f4 / 10) * 44 + (f4 % 10) * 4] = v;
            }
        }
    }
    __syncwarp();

    // agg[j] = (last 3 of float4[j-1]) + (first 3 of float4[j]), rolling window
    float agg[10];
    if (FULL || lane < nv) {
        const unsigned mx = saddr(&buf[lane * 44]);
        float4 vp = lds128a(mx + 9 * 16);
        #pragma unroll
        for (int j = 0; j < 10; j++) {
            float4 v = lds128a(mx + j * 16);
            agg[j] = (vp.y + vp.z) + (vp.w + v.x) + (v.y + v.z);
            vp = v;
        }
    }
    __syncwarp();

    // ===== stage z (coalesced, streaming), rows padded to 84 floats =====
    {
        const float4* zg = (const float4*)(z + e0 * 80);
        const int lim = nv * 20;
        #pragma unroll
        for (int k = 0; k < 20; k++) {
            int f4 = k * 32 + lane;
            if (FULL || f4 < lim) {
                float4 v = __ldcs(&zg[f4]);
                *(float4*)&buf[(f4 / 20) * 84 + (f4 % 20) * 4] = v;
            }
        }
    }
    __syncwarp();

    float s[10];
    if (FULL || lane < nv) {
        const unsigned zr_a = saddr(&buf[lane * 84]);
        const ull*    er2 = (const ull*)(cW + C_ER);    // 4 pairs per f
        const float2* ewb = (const float2*)(cW + C_EWB);

        // ---- encoder: 2-node blocking, packed-over-g dot products ----
        #pragma unroll
        for (int p = 0; p < 5; p++) {
            const int j0 = 2 * p, j1 = 2 * p + 1;
            ull z0p[4], z1p[4];
            load_row_p(zr_a + j0 * 32, z0p);
            load_row_p(zr_a + j1 * 32, z1p);
            float t0[8], t1[8];
            #pragma unroll
            for (int f = 0; f < 8; f++) {
                float2 wb = ewb[f];             // {erw[f], erb[f]}
                ull w0 = er2[f * 4], w1 = er2[f * 4 + 1], w2 = er2[f * 4 + 2], w3 = er2[f * 4 + 3];
                ull a0 = pack2(fmaf(agg[j0], wb.x, wb.y), 0.0f);
                ull a1 = pack2(fmaf(agg[j1], wb.x, wb.y), 0.0f);
                a0 = ffma2(z0p[0], w0, a0); a0 = ffma2(z0p[1], w1, a0);
                a0 = ffma2(z0p[2], w2, a0); a0 = ffma2(z0p[3], w3, a0);
                a1 = ffma2(z1p[0], w0, a1); a1 = ffma2(z1p[1], w1, a1);
                a1 = ffma2(z1p[2], w2, a1); a1 = ffma2(z1p[3], w3, a1);
                t0[f] = fmaxf(hsum2(a0), 0.0f);
                t1[f] = fmaxf(hsum2(a1), 0.0f);
            }
            sts128a(zr_a + j0 * 32,      make_float4(t0[0], t0[1], t0[2], t0[3]));
            sts128a(zr_a + j0 * 32 + 16, make_float4(t0[4], t0[5], t0[6], t0[7]));
            sts128a(zr_a + j1 * 32,      make_float4(t1[0], t1[1], t1[2], t1[3]));
            sts128a(zr_a + j1 * 32 + 16, make_float4(t1[4], t1[5], t1[6], t1[7]));
        }

        // ---- predictor: 2-node blocking, 4-row rolling window, packed ----
        // nodes (2p+1, 2p+2): t = M1@center + M2@(neighbor sum) + prb
        const ull*    m1p = (const ull*)(cW + C_M1);
        const ull*    m2p = (const ull*)(cW + C_M2);
        const float2* pbd = (const float2*)(cW + C_PBD);
        ull r0[4], r1[4], r2[4], r3[4];
        load_row_p(zr_a + 0,  r0);    // z1[0]
        load_row_p(zr_a + 32, r1);    // z1[1]
        #pragma unroll
        for (int p = 0; p < 5; p++) {
            const int n1 = (2 * p + 1) % 10;
            const int n2 = (2 * p + 2) % 10;
            load_row_p(zr_a + ((2 * p + 2) % 10) * 32, r2);
            load_row_p(zr_a + ((2 * p + 3) % 10) * 32, r3);
            ull u1[4], u2[4];
            #pragma unroll
            for (int k = 0; k < 4; k++) { u1[k] = fadd2(r0[k], r2[k]); u2[k] = fadd2(r1[k], r3[k]); }
            float s1e = 0.0f, s1o = 0.0f, s2e = 0.0f, s2o = 0.0f;
            #pragma unroll
            for (int f = 0; f < 8; f++) {
                float2 bd = pbd[f];             // {prb[f], drw[f]}
                ull a0 = m1p[f * 4], a1 = m1p[f * 4 + 1], a2 = m1p[f * 4 + 2], a3 = m1p[f * 4 + 3];
                ull b0 = m2p[f * 4], b1 = m2p[f * 4 + 1], b2 = m2p[f * 4 + 2], b3 = m2p[f * 4 + 3];
                ull bias0 = pack2(bd.x, 0.0f);
                // node n1: center r1, nsum u1 (two independent chains)
                ull c1 = ffma2(r1[0], a0, bias0); c1 = ffma2(r1[1], a1, c1);
                c1 = ffma2(r1[2], a2, c1);        c1 = ffma2(r1[3], a3, c1);
                ull d1 = ffma2(u1[1], b1, ffma2(u1[0], b0, 0ULL));
                d1 = ffma2(u1[2], b2, d1);        d1 = ffma2(u1[3], b3, d1);
                float t1 = fmaxf(hsum2(c1) + hsum2(d1), 0.0f);
                // node n2: center r2, nsum u2
                ull c2 = ffma2(r2[0], a0, bias0); c2 = ffma2(r2[1], a1, c2);
                c2 = ffma2(r2[2], a2, c2);        c2 = ffma2(r2[3], a3, c2);
                ull d2 = ffma2(u2[1], b1, ffma2(u2[0], b0, 0ULL));
                d2 = ffma2(u2[2], b2, d2);        d2 = ffma2(u2[3], b3, d2);
                float t2 = fmaxf(hsum2(c2) + hsum2(d2), 0.0f);
                if (f & 1) { s1o = fmaf(t1, bd.y, s1o); s2o = fmaf(t2, bd.y, s2o); }
                else       { s1e = fmaf(t1, bd.y, s1e); s2e = fmaf(t2, bd.y, s2e); }
            }
            s[n1] = s1e + s1o;
            s[n2] = s2e + s2o;
            #pragma unroll
            for (int k = 0; k < 4; k++) { r0[k] = r2[k]; r1[k] = r3[k]; }
        }
    }
    __syncwarp();   // all pred reads of z1 done -> safe to overwrite via alias

    if (FULL || lane < nv) {
        #pragma unroll
        for (int j = 0; j < 10; j++)
            ss[lane * 11 + j] = s[j];
    }
    __syncwarp();

    // ===== decoder: y streamed from gmem, out written directly, coalesced =====
    {
        const float4* yg = (const float4*)(y + e0 * 40);
        float4* og = (float4*)(out + e0 * 40);
        const float drb = cW[C_DRB], drt = cW[C_DRT];
        const int lim = nv * 10;
        #pragma unroll
        for (int k = 0; k < 10; k++) {
            int f4 = k * 32 + lane;
            if (FULL || f4 < lim) {
                const int e = f4 / 10, c = f4 % 10;
                float4 v = __ldcs(&yg[f4]);
                const float s0 = ss[e * 11 + c];
                const float s1 = ss[e * 11 + ((c + 1) % 10)];
                const float c12 = s0 + s1;
                v.x = fmaf(v.x, drt, drb) + s0;
                v.y = fmaf(v.y, drt, drb) + c12;
                v.z = fmaf(v.z, drt, drb) + c12;
                v.w = fmaf(v.w, drt, drb) + s1;
                __stcs(&og[f4], v);
            }
        }
    }
}

__global__ void __launch_bounds__(128, 5)
fused_gnn_kernel(const float* __restrict__ x,
                 const float* __restrict__ z,
                 const float* __restrict__ y,
                 float* __restrict__ out,
                 long long B)
{
    __shared__ __align__(16) float4 sbuf4[4][672];  // per warp: 32 rows x 84 floats

    const int tid = threadIdx.x;
    const int warp = tid >> 5;
    const int lane = tid & 31;
    const long long e0 = ((long long)blockIdx.x * 4 + warp) * 32;
    if (e0 >= B) return;
    float* buf = (float*)sbuf4[warp];

    if (B - e0 >= 32) {
        body<true>(x, z, y, out, buf, lane, e0, 32);
    } else {
        body<false>(x, z, y, out, buf, lane, e0, (int)(B - e0));
    }
}

extern "C" void kernel_launch(void* const* d_in, const int* in_sizes, int n_in,
                              void* d_out, int out_size)
{
    const float* x = (const float*)d_in[0];
    const float* z = (const float*)d_in[1];
    const float* y = (const float*)d_in[2];

    // 1) pack + pre-transform weights into contiguous device staging
    gather_weights<<<1, 64>>>(
        (const float*)d_in[3], (const float*)d_in[4], (const float*)d_in[5],
        (const float*)d_in[6], (const float*)d_in[7], (const float*)d_in[8],
        (const float*)d_in[9], (const float*)d_in[10], (const float*)d_in[11]);

    // 2) one D2D memcpy into __constant__ (graph-capturable)
    void* stage_ptr = nullptr;
    cudaGetSymbolAddress(&stage_ptr, gStage);
    cudaMemcpyToSymbolAsync(cW, stage_ptr, 232 * sizeof(float), 0,
                            cudaMemcpyDeviceToDevice, 0);

    const long long B = (long long)in_sizes[0] / 40;
    const int threads = 128;                      // 4 warps x 32 elements
    const long long elems_per_block = 128;
    const int blocks = (int)((B + elems_per_block - 1) / elems_per_block);

    fused_gnn_kernel<<<blocks, threads>>>(x, z, y, (float*)d_out, B);
}

// round 16
// speedup vs baseline: 1.1048x; 1.1048x over previous
#include <cuda_runtime.h>

// Fused 3-layer GraphConv, B=524288.
//   A_ENC:  agg[j]  = sum_{i=4j-3..4j+2} x[i mod 40]
//   A_PRED: agg2[j] = z1[j] + w*(z1[j-1] + z1[j+1]),  w = exp(-1/9)
//   A_DEC:  out[4k]=s[k], out[4k+1]=out[4k+2]=s[k]+s[k+1], out[4k+3]=s[k+1]
//           with s[j] = dot(relu(pred(z1)[j]), dec_rel_w)
//
// R15 = R13 (best kernel 115.6us; f32x2 of R14 retired — less ILP, more stall)
//  + cp.async.cg staging (no LDG->STS register chaining, ~28 fewer issue
//    slots/thread, streaming L2-only like __ldcs)
//  + 96-thread blocks, launch_bounds(96,7): 21 warps/SM (the smem+reg wall
//    is ~21 warps; 4-warp blocks quantized to 20). No block syncs exist.

#define WPRED 0.8948393168143698f

__constant__ __align__(16) float cW[232];
#define C_ER   0     // enc_root_w  [f*8+g]
#define C_M1   64    // PR + PO
#define C_M2   128   // WPRED * PR
#define C_EWB  192   // float2 pairs {erw[f], erb[f]}  (16 floats)
#define C_PBD  208   // float2 pairs {prb[f], drw[f]}  (16 floats)
#define C_DRB  224
#define C_DRT  225

__device__ __align__(16) float gStage[232];

__global__ void gather_weights(const float* __restrict__ erw, const float* __restrict__ erb,
                               const float* __restrict__ er,  const float* __restrict__ pr,
                               const float* __restrict__ prb, const float* __restrict__ po,
                               const float* __restrict__ drw, const float* __restrict__ drb,
                               const float* __restrict__ drt)
{
    const int t = threadIdx.x;
    if (t < 64) {
        gStage[C_ER + t] = er[t];
        gStage[C_M1 + t] = pr[t] + po[t];
        gStage[C_M2 + t] = WPRED * pr[t];
    }
    if (t < 8) {
        gStage[C_EWB + 2 * t]     = erw[t];
        gStage[C_EWB + 2 * t + 1] = erb[t];
        gStage[C_PBD + 2 * t]     = prb[t];
        gStage[C_PBD + 2 * t + 1] = drw[t];
    }
    if (t == 0) { gStage[C_DRB] = drb[0]; gStage[C_DRT] = drt[0]; }
}

__device__ __forceinline__ float4 lds128a(unsigned a) {
    float4 r;
    asm volatile("ld.shared.v4.f32 {%0,%1,%2,%3}, [%4];"
                 : "=f"(r.x), "=f"(r.y), "=f"(r.z), "=f"(r.w) : "r"(a));
    return r;
}
__device__ __forceinline__ void sts128a(unsigned a, float4 v) {
    asm volatile("st.shared.v4.f32 [%0], {%1,%2,%3,%4};"
                 :: "r"(a), "f"(v.x), "f"(v.y), "f"(v.z), "f"(v.w));
}
__device__ __forceinline__ unsigned saddr(const void* p) {
    return (unsigned)__cvta_generic_to_shared(p);
}
__device__ __forceinline__ void cpasync16(unsigned dst, const void* src) {
    asm volatile("cp.async.cg.shared.global [%0], [%1], 16;"
                 :: "r"(dst), "l"(src) : "memory");
}
#define CP_COMMIT() asm volatile("cp.async.commit_group;" ::: "memory")
#define CP_WAIT0()  asm volatile("cp.async.wait_group 0;" ::: "memory")

template <bool FULL>
__device__ __forceinline__ void body(const float* __restrict__ x,
                                     const float* __restrict__ z,
                                     const float* __restrict__ y,
                                     float* __restrict__ out,
                                     float* buf, int lane, long long e0, int nv)
{
    float* ss = buf;   // alias: reused after z1 dead (32 x stride-11 floats)
    const unsigned buf_a = saddr(buf);

    // ===== stage x via cp.async (streaming), rows padded to 44 floats =====
    {
        const float4* xg = (const float4*)(x + e0 * 40);
        const int lim = nv * 10;
        #pragma unroll
        for (int k = 0; k < 10; k++) {
            int f4 = k * 32 + lane;
            if (FULL || f4 < lim)
                cpasync16(buf_a + ((f4 / 10) * 44 + (f4 % 10) * 4) * 4, xg + f4);
        }
    }
    CP_COMMIT();
    CP_WAIT0();
    __syncwarp();

    // agg[j] = (last 3 of float4[j-1]) + (first 3 of float4[j]), rolling window
    float agg[10];
    if (FULL || lane < nv) {
        const unsigned mx = buf_a + lane * 44 * 4;
        float4 vp = lds128a(mx + 9 * 16);
        #pragma unroll
        for (int j = 0; j < 10; j++) {
            float4 v = lds128a(mx + j * 16);
            agg[j] = (vp.y + vp.z) + (vp.w + v.x) + (v.y + v.z);
            vp = v;
        }
    }
    __syncwarp();   // all agg reads done before z overwrites the x region

    // ===== stage z via cp.async (streaming), rows padded to 84 floats =====
    {
        const float4* zg = (const float4*)(z + e0 * 80);
        const int lim = nv * 20;
        #pragma unroll
        for (int k = 0; k < 20; k++) {
            int f4 = k * 32 + lane;
            if (FULL || f4 < lim)
                cpasync16(buf_a + ((f4 / 20) * 84 + (f4 % 20) * 4) * 4, zg + f4);
        }
    }
    CP_COMMIT();
    CP_WAIT0();
    __syncwarp();

    float s[10];
    if (FULL || lane < nv) {
        const unsigned zr_a = buf_a + lane * 84 * 4;
        const float4*  er4 = (const float4*)(cW + C_ER);
        const float2*  ewb = (const float2*)(cW + C_EWB);

        // ---- encoder: 2-node blocking, z1 overwrites z in smem ----
        #pragma unroll
        for (int p = 0; p < 5; p++) {
            const int j0 = 2 * p, j1 = 2 * p + 1;
            float4 a0 = lds128a(zr_a + j0 * 32);
            float4 b0 = lds128a(zr_a + j0 * 32 + 16);
            float4 a1 = lds128a(zr_a + j1 * 32);
            float4 b1 = lds128a(zr_a + j1 * 32 + 16);
            float t0[8], t1[8];
            #pragma unroll
            for (int f = 0; f < 8; f++) {
                float4 w0 = er4[f * 2], w1 = er4[f * 2 + 1];
                float2 wb = ewb[f];             // {erw[f], erb[f]}
                float c0 = fmaf(a0.x, w0.x, fmaf(a0.y, w0.y,
                           fmaf(a0.z, w0.z, fmaf(a0.w, w0.w,
                           fmaf(agg[j0], wb.x, wb.y)))));
                float c1 = fmaf(b0.x, w1.x, fmaf(b0.y, w1.y, fmaf(b0.z, w1.z, b0.w * w1.w)));
                t0[f] = fmaxf(c0 + c1, 0.0f);
                float d0 = fmaf(a1.x, w0.x, fmaf(a1.y, w0.y,
                           fmaf(a1.z, w0.z, fmaf(a1.w, w0.w,
                           fmaf(agg[j1], wb.x, wb.y)))));
                float d1 = fmaf(b1.x, w1.x, fmaf(b1.y, w1.y, fmaf(b1.z, w1.z, b1.w * w1.w)));
                t1[f] = fmaxf(d0 + d1, 0.0f);
            }
            sts128a(zr_a + j0 * 32,      make_float4(t0[0], t0[1], t0[2], t0[3]));
            sts128a(zr_a + j0 * 32 + 16, make_float4(t0[4], t0[5], t0[6], t0[7]));
            sts128a(zr_a + j1 * 32,      make_float4(t1[0], t1[1], t1[2], t1[3]));
            sts128a(zr_a + j1 * 32 + 16, make_float4(t1[4], t1[5], t1[6], t1[7]));
        }

        // ---- predictor: 2-node blocking, 4-row rolling window ----
        // nodes (2p+1, 2p+2): t = M1@center + M2@(neighbor sum) + prb
        const float4* m14 = (const float4*)(cW + C_M1);
        const float4* m24 = (const float4*)(cW + C_M2);
        const float2* pbd = (const float2*)(cW + C_PBD);
        float4 r0a = lds128a(zr_a + 0);        // z1[0]
        float4 r0b = lds128a(zr_a + 16);
        float4 r1a = lds128a(zr_a + 32);       // z1[1]
        float4 r1b = lds128a(zr_a + 48);
        #pragma unroll
        for (int p = 0; p < 5; p++) {
            const int n1 = (2 * p + 1) % 10;   // node indices
            const int n2 = (2 * p + 2) % 10;
            const int i2 = (2 * p + 2) % 10;   // row indices to load
            const int i3 = (2 * p + 3) % 10;
            float4 r2a = lds128a(zr_a + i2 * 32);
            float4 r2b = lds128a(zr_a + i2 * 32 + 16);
            float4 r3a = lds128a(zr_a + i3 * 32);
            float4 r3b = lds128a(zr_a + i3 * 32 + 16);
            // neighbor sums
            float4 u1a = make_float4(r0a.x + r2a.x, r0a.y + r2a.y, r0a.z + r2a.z, r0a.w + r2a.w);
            float4 u1b = make_float4(r0b.x + r2b.x, r0b.y + r2b.y, r0b.z + r2b.z, r0b.w + r2b.w);
            float4 u2a = make_float4(r1a.x + r3a.x, r1a.y + r3a.y, r1a.z + r3a.z, r1a.w + r3a.w);
            float4 u2b = make_float4(r1b.x + r3b.x, r1b.y + r3b.y, r1b.z + r3b.z, r1b.w + r3b.w);
            float s1e = 0.0f, s1o = 0.0f, s2e = 0.0f, s2o = 0.0f;
            #pragma unroll
            for (int f = 0; f < 8; f++) {
                float4 a0 = m14[f * 2], a1 = m14[f * 2 + 1];
                float4 b0 = m24[f * 2], b1 = m24[f * 2 + 1];
                float2 bd = pbd[f];             // {prb[f], drw[f]}
                // node n1: center (r1), nsum (u1)
                float p0 = fmaf(r1a.x, a0.x, fmaf(r1a.y, a0.y, fmaf(r1a.z, a0.z, fmaf(r1a.w, a0.w, bd.x))));
                float p1 = fmaf(r1b.x, a1.x, fmaf(r1b.y, a1.y, fmaf(r1b.z, a1.z, r1b.w * a1.w)));
                float p2 = fmaf(u1a.x, b0.x, fmaf(u1a.y, b0.y, fmaf(u1a.z, b0.z, u1a.w * b0.w)));
                float p3 = fmaf(u1b.x, b1.x, fmaf(u1b.y, b1.y, fmaf(u1b.z, b1.z, u1b.w * b1.w)));
                float t1 = fmaxf((p0 + p1) + (p2 + p3), 0.0f);
                // node n2: center (r2), nsum (u2)
                float q0 = fmaf(r2a.x, a0.x, fmaf(r2a.y, a0.y, fmaf(r2a.z, a0.z, fmaf(r2a.w, a0.w, bd.x))));
                float q1 = fmaf(r2b.x, a1.x, fmaf(r2b.y, a1.y, fmaf(r2b.z, a1.z, r2b.w * a1.w)));
                float q2 = fmaf(u2a.x, b0.x, fmaf(u2a.y, b0.y, fmaf(u2a.z, b0.z, u2a.w * b0.w)));
                float q3 = fmaf(u2b.x, b1.x, fmaf(u2b.y, b1.y, fmaf(u2b.z, b1.z, u2b.w * b1.w)));
                float t2 = fmaxf((q0 + q1) + (q2 + q3), 0.0f);
                if (f & 1) { s1o = fmaf(t1, bd.y, s1o); s2o = fmaf(t2, bd.y, s2o); }
                else       { s1e = fmaf(t1, bd.y, s1e); s2e = fmaf(t2, bd.y, s2e); }
            }
            s[n1] = s1e + s1o;
            s[n2] = s2e + s2o;
            r0a = r2a; r0b = r2b; r1a = r3a; r1b = r3b;
        }
    }
    __syncwarp();   // all pred reads of z1 done -> safe to overwrite via alias

    if (FULL || lane < nv) {
        #pragma unroll
        for (int j = 0; j < 10; j++)
            ss[lane * 11 + j] = s[j];
    }
    __syncwarp();

    // ===== decoder: y streamed from gmem, out written directly, coalesced =====
    {
        const float4* yg = (const float4*)(y + e0 * 40);
        float4* og = (float4*)(out + e0 * 40);
        const float drb = cW[C_DRB], drt = cW[C_DRT];
        const int lim = nv * 10;
        #pragma unroll
        for (int k = 0; k < 10; k++) {
            int f4 = k * 32 + lane;
            if (FULL || f4 < lim) {
                const int e = f4 / 10, c = f4 % 10;
                float4 v = __ldcs(&yg[f4]);
                const float s0 = ss[e * 11 + c];
                const float s1 = ss[e * 11 + ((c + 1) % 10)];
                const float c12 = s0 + s1;
                v.x = fmaf(v.x, drt, drb) + s0;
                v.y = fmaf(v.y, drt, drb) + c12;
                v.z = fmaf(v.z, drt, drb) + c12;
                v.w = fmaf(v.w, drt, drb) + s1;
                __stcs(&og[f4], v);
            }
        }
    }
}

__global__ void __launch_bounds__(96, 7)
fused_gnn_kernel(const float* __restrict__ x,
                 const float* __restrict__ z,
                 const float* __restrict__ y,
                 float* __restrict__ out,
                 long long B)
{
    __shared__ __align__(16) float4 sbuf4[3][672];  // per warp: 32 rows x 84 floats

    const int tid = threadIdx.x;
    const int warp = tid >> 5;
    const int lane = tid & 31;
    const long long e0 = ((long long)blockIdx.x * 3 + warp) * 32;
    if (e0 >= B) return;
    float* buf = (float*)sbuf4[warp];

    if (B - e0 >= 32) {
        body<true>(x, z, y, out, buf, lane, e0, 32);
    } else {
        body<false>(x, z, y, out, buf, lane, e0, (int)(B - e0));
    }
}

extern "C" void kernel_launch(void* const* d_in, const int* in_sizes, int n_in,
                              void* d_out, int out_size)
{
    const float* x = (const float*)d_in[0];
    const float* z = (const float*)d_in[1];
    const float* y = (const float*)d_in[2];

    // 1) pack + pre-transform weights into contiguous device staging
    gather_weights<<<1, 64>>>(
        (const float*)d_in[3], (const float*)d_in[4], (const float*)d_in[5],
        (const float*)d_in[6], (const float*)d_in[7], (const float*)d_in[8],
        (const float*)d_in[9], (const float*)d_in[10], (const float*)d_in[11]);

    // 2) one D2D memcpy into __constant__ (graph-capturable)
    void* stage_ptr = nullptr;
    cudaGetSymbolAddress(&stage_ptr, gStage);
    cudaMemcpyToSymbolAsync(cW, stage_ptr, 232 * sizeof(float), 0,
                            cudaMemcpyDeviceToDevice, 0);

    const long long B = (long long)in_sizes[0] / 40;
    const int threads = 96;                       // 3 warps x 32 elements
    const long long elems_per_block = 96;
    const int blocks = (int)((B + elems_per_block - 1) / elems_per_block);

    fused_gnn_kernel<<<blocks, threads>>>(x, z, y, (float*)d_out, B);
}